// round 5
// baseline (speedup 1.0000x reference)
#include <cuda_runtime.h>
#include <math.h>

// Problem dims
#define S  64
#define H  1024
#define V  512
#define WV 300
#define NE 512

// Recurrent kernel config
#define RB  64   // blocks; each owns RC columns of ev and 8 entities in stage B
#define RC  16
#define RT  512

// Output offsets (reference return order)
#define OFF_ENTP 0
#define OFF_ACP  (S*NE)
#define OFF_ENT  (OFF_ACP + S*V)
#define OFF_ALL  (OFF_ENT + S*H)
#define OFF_ACT  (OFF_ALL + (size_t)S*NE*H)

// Scratch (device globals; no allocation allowed)
__device__ __align__(16) float g_HH[64*2048];     // dense [relu(h) | relu(hat)]
__device__ __align__(16) float g_ACd[64*512];     // dense sigmoid(ac)
__device__ __align__(16) float g_GP3[8*64*1024];  // w2v split-K partials
__device__ __align__(16) float g_W2V[S*H];
__device__ float g_CHOICE[S*2];
__device__ float g_SCAL[S];
__device__ __align__(16) float g_PART[RB*NE];     // logit partials [part_block][entity]
__device__ __align__(16) float g_ENT[NE];         // finalized ent of current step
__device__ __align__(16) float g_SSUM8[RB];       // per-block 8-entity ent sums
__device__ unsigned g_barcnt;
__device__ unsigned g_bargen;

// ---------------------------------------------------------------------------
// Dense split-N GEMM: Out[64,N] = act( X[64,K] @ W[N,K]^T + b )
// Block (0,0) thread 0 also resets the grid barrier (safe: runs first).
// ---------------------------------------------------------------------------
__global__ void __launch_bounds__(256) gemm32(
    const float* __restrict__ X, int xstride,
    const float* __restrict__ Wa, const float* __restrict__ Wb, int NB,
    const float* __restrict__ bA, const float* __restrict__ bB,
    float* __restrict__ Out, int ostride, int K, int act)
{
    if (blockIdx.x == 0 && blockIdx.y == 0 && threadIdx.x == 0) {
        g_barcnt = 0; g_bargen = 0;
    }
    __shared__ __align__(8) float Xs[32][34];
    __shared__ __align__(8) float Ws[32][34];
    int tid = threadIdx.x;
    int tx = tid & 15, ty = tid >> 4;
    int n0 = blockIdx.x * 32;
    int m0 = blockIdx.y * 32;

    float a00 = 0.f, a01 = 0.f, a10 = 0.f, a11 = 0.f;

    for (int kc = 0; kc < K; kc += 32) {
#pragma unroll
        for (int i = 0; i < 4; i++) {
            int e = tid + 256*i; int row = e >> 5, kk = e & 31;
            Xs[kk][row] = X[(size_t)(m0 + row)*xstride + kc + kk];
        }
#pragma unroll
        for (int i = 0; i < 4; i++) {
            int e = tid + 256*i; int nr = e >> 5, kk = e & 31;
            int n = n0 + nr;
            const float* Wp = (n < NB) ? (Wa + (size_t)n*K) : (Wb + (size_t)(n - NB)*K);
            Ws[kk][nr] = Wp[kc + kk];
        }
        __syncthreads();
#pragma unroll
        for (int kk = 0; kk < 32; kk++) {
            float x0 = Xs[kk][ty*2], x1 = Xs[kk][ty*2+1];
            float w0 = Ws[kk][tx*2], w1 = Ws[kk][tx*2+1];
            a00 += x0*w0; a01 += x0*w1;
            a10 += x1*w0; a11 += x1*w1;
        }
        __syncthreads();
    }

    int n = n0 + tx*2;
    float b0 = (n   < NB) ? bA[n]   : bB[n   - NB];
    float b1 = (n+1 < NB) ? bA[n+1] : bB[n+1 - NB];
    float r[2][2] = {{a00 + b0, a01 + b1}, {a10 + b0, a11 + b1}};
#pragma unroll
    for (int q = 0; q < 2; q++)
#pragma unroll
        for (int p = 0; p < 2; p++) {
            float v = r[q][p];
            if (act == 1)      v = fmaxf(v, 0.f);
            else if (act == 2) v = 1.f/(1.f + expf(-v));
            Out[(size_t)(m0 + ty*2 + q)*ostride + n0 + tx*2 + p] = v;
        }
}

// ---------------------------------------------------------------------------
// Split-K GEMM for w2v partials: GP3[ky][64][1024] = [relu(hat)|sig(ac)] @ W2w^T
// ---------------------------------------------------------------------------
__global__ void __launch_bounds__(256) gemm3(
    const float* __restrict__ W, float* __restrict__ OutP, int N, int K, int kslice)
{
    __shared__ __align__(16) float XsT[32][68];
    __shared__ __align__(16) float WsT[32][68];
    int tid = threadIdx.x;
    int tx = tid & 15, ty = tid >> 4;
    int n0 = blockIdx.x * 64;
    int kc0 = blockIdx.y * kslice;

    float acc[4][4];
#pragma unroll
    for (int r = 0; r < 4; r++)
#pragma unroll
        for (int q = 0; q < 4; q++) acc[r][q] = 0.f;

    for (int kc = kc0; kc < kc0 + kslice; kc += 32) {
#pragma unroll
        for (int i = 0; i < 8; i++) {
            int e = tid + 256*i; int row = e >> 5, kk = e & 31;
            int k = kc + kk;
            XsT[kk][row] = (k < 1024) ? g_HH[row*2048 + 1024 + k]
                                      : g_ACd[row*512 + (k - 1024)];
        }
#pragma unroll
        for (int i = 0; i < 8; i++) {
            int e = tid + 256*i; int nr = e >> 5, kk = e & 31;
            WsT[kk][nr] = W[(size_t)(n0 + nr)*K + kc + kk];
        }
        __syncthreads();
#pragma unroll
        for (int kk = 0; kk < 32; kk++) {
            float4 xa = *(const float4*)&XsT[kk][ty*4];
            float4 wb = *(const float4*)&WsT[kk][tx*4];
            acc[0][0] += xa.x*wb.x; acc[0][1] += xa.x*wb.y; acc[0][2] += xa.x*wb.z; acc[0][3] += xa.x*wb.w;
            acc[1][0] += xa.y*wb.x; acc[1][1] += xa.y*wb.y; acc[1][2] += xa.y*wb.z; acc[1][3] += xa.y*wb.w;
            acc[2][0] += xa.z*wb.x; acc[2][1] += xa.z*wb.y; acc[2][2] += xa.z*wb.z; acc[2][3] += xa.z*wb.w;
            acc[3][0] += xa.w*wb.x; acc[3][1] += xa.w*wb.y; acc[3][2] += xa.w*wb.z; acc[3][3] += xa.w*wb.w;
        }
        __syncthreads();
    }
    float* Po = OutP + (size_t)blockIdx.y*64*N + n0;
#pragma unroll
    for (int r = 0; r < 4; r++) {
        float4 v = make_float4(acc[r][0], acc[r][1], acc[r][2], acc[r][3]);
        *(float4*)&Po[(size_t)(ty*4 + r)*N + tx*4] = v;
    }
}

// ---------------------------------------------------------------------------
// Release/acquire grid barrier (RB blocks all resident). acq_rel arrival so the
// releasing block's generation store transitively orders all arrivals' writes.
// ---------------------------------------------------------------------------
__device__ __forceinline__ void gridbar(unsigned target)
{
    __syncthreads();
    if (threadIdx.x == 0) {
        unsigned prev;
        asm volatile("atom.acq_rel.gpu.global.add.u32 %0, [%1], 1;"
                     : "=r"(prev) : "l"(&g_barcnt) : "memory");
        if (prev == RB - 1) {
            g_barcnt = 0;
            asm volatile("st.release.gpu.global.u32 [%0], %1;"
                         :: "l"(&g_bargen), "r"(target) : "memory");
        } else {
            unsigned cur;
            do {
                asm volatile("ld.acquire.gpu.global.u32 %0, [%1];"
                             : "=r"(cur) : "l"(&g_bargen) : "memory");
            } while (cur < target);
        }
    }
    __syncthreads();
}

// ---------------------------------------------------------------------------
// Stage B: finalize ent for step tt. Block blk reduces entities [8blk, 8blk+8)
// across all 64 blocks' partials; writes g_ENT, ent_probs out row, g_SSUM8.
// ---------------------------------------------------------------------------
__device__ __forceinline__ void stageB(int blk, int tid, int tt,
                                       float* __restrict__ out,
                                       float* __restrict__ s_stb /*[16*8]*/)
{
    int p = tid >> 3, e = tid & 7;
    int lane = tid & 31, wid = tid >> 5;
    float v = __ldcg(&g_PART[p*NE + blk*8 + e]);
    v += __shfl_xor_sync(0xffffffffu, v, 8);
    v += __shfl_xor_sync(0xffffffffu, v, 16);
    if (lane < 8) s_stb[wid*8 + lane] = v;
    __syncthreads();
    if (tid < 8) {
        float lg = 0.f;
#pragma unroll
        for (int w = 0; w < 16; w++) lg += s_stb[w*8 + tid];
        float ent = 1.f/(1.f + expf(-lg));
        g_ENT[blk*8 + tid] = ent;
        out[OFF_ENTP + tt*NE + blk*8 + tid] = ent;
        float s8 = ent;
        s8 += __shfl_xor_sync(0xffu, s8, 4);
        s8 += __shfl_xor_sync(0xffu, s8, 2);
        s8 += __shfl_xor_sync(0xffu, s8, 1);
        if (tid == 0) g_SSUM8[blk] = s8;
    }
}

// ---------------------------------------------------------------------------
// Persistent recurrent kernel (launch index 3; profiled).
// Prologue: per-block smalls (t=blk) + w2v reduce; logit0 partials; stage B.
// Loop: two-stage logit reduction, smem-transpose row reductions, register ev.
// ---------------------------------------------------------------------------
__global__ void __launch_bounds__(RT, 1) k_recurrent(
    const float* __restrict__ evin,
    const float* __restrict__ emb,
    const float* __restrict__ W2b,
    const float* __restrict__ W3w, const float* __restrict__ W3b,
    const float* __restrict__ W4w, const float* __restrict__ W4b,
    float* __restrict__ out)
{
    int tid = threadIdx.x;
    int blk = blockIdx.x;
    int c = tid & 15, s = tid >> 4;
    int j = blk*RC + c;
    int i0 = s*16;
    int lane = tid & 31, wid = tid >> 5;

    __shared__ float s_attn[NE];
    __shared__ float s_mat[NE*17];        // row-major padded transpose scratch
    __shared__ float s_part[32*17];
    __shared__ float s_kt[RC];
    __shared__ float s_red[16];
    __shared__ float s_r2[2];
    __shared__ float s_stb[16*8];
    __shared__ float s_sum;
    __shared__ float s_ac[V];
    __shared__ float s_bf[WV];
    __shared__ float s_cl[3];

    // issue ev load early (DRAM latency overlaps the smalls below)
    float evr[16];
#pragma unroll
    for (int r = 0; r < 16; r++) evr[r] = evin[(size_t)(i0 + r)*H + j];

    // ================= prologue: smalls for step t = blk =================
    {
        int t = blk;
        float a = g_ACd[t*V + tid];
        s_ac[tid] = a;
        out[OFF_ACP + t*V + tid] = a;
        float v = a;
#pragma unroll
        for (int o = 16; o; o >>= 1) v += __shfl_xor_sync(0xffffffffu, v, o);
        if (lane == 0) s_red[wid] = v;
        __syncthreads();
        if (tid < 16) {
            float x = s_red[tid];
#pragma unroll
            for (int o = 8; o; o >>= 1) x += __shfl_xor_sync(0x0000ffffu, x, o);
            if (tid == 0) s_sum = x;
        }
        __syncthreads();
        float acsum = s_sum;

        if (tid < WV) {
            float a0 = 0.f, a1 = 0.f, a2 = 0.f, a3 = 0.f;
            for (int i = 0; i < V; i += 4) {
                a0 += s_ac[i+0]*emb[(i+0)*WV + tid];
                a1 += s_ac[i+1]*emb[(i+1)*WV + tid];
                a2 += s_ac[i+2]*emb[(i+2)*WV + tid];
                a3 += s_ac[i+3]*emb[(i+3)*WV + tid];
            }
            float bf = ((a0+a1)+(a2+a3)) / acsum;
            s_bf[tid] = bf;
            out[OFF_ACT + t*WV + tid] = bf;
        }
        __syncthreads();

        float p = (tid < WV) ? s_bf[tid]*W4w[tid] : 0.f;
#pragma unroll
        for (int o = 16; o; o >>= 1) p += __shfl_xor_sync(0xffffffffu, p, o);
        if (lane == 0) s_red[wid] = p;
        __syncthreads();
        if (tid < 16) {
            float x = s_red[tid];
#pragma unroll
            for (int o = 8; o; o >>= 1) x += __shfl_xor_sync(0x0000ffffu, x, o);
            if (tid == 0) g_SCAL[t] = x + W4b[0];
        }

        if (wid < 3) {
            float a3v = 0.f;
            for (int k = lane; k < H; k += 32)
                a3v += g_HH[t*2048 + 1024 + k]*W3w[wid*H + k];
#pragma unroll
            for (int o = 16; o; o >>= 1) a3v += __shfl_xor_sync(0xffffffffu, a3v, o);
            if (lane == 0) s_cl[wid] = a3v + W3b[wid];
        }
        __syncthreads();
        if (tid == 0) {
            float m = fmaxf(s_cl[0], fmaxf(s_cl[1], s_cl[2]));
            float e0 = expf(s_cl[0]-m), e1 = expf(s_cl[1]-m), e2 = expf(s_cl[2]-m);
            float sm = e0 + e1 + e2;
            g_CHOICE[t*2+0] = e0/sm;
            g_CHOICE[t*2+1] = e1/sm;
        }

        // w2v[t] = W2b + sum_ky GP3[ky][t][:]
#pragma unroll
        for (int h2 = 0; h2 < 2; h2++) {
            int n = tid + 512*h2;
            float w = W2b[n];
#pragma unroll
            for (int ky = 0; ky < 8; ky++) w += g_GP3[ky*64*1024 + t*1024 + n];
            g_W2V[t*H + n] = w;
        }
    }
    gridbar(1);

    // logit0 partials via smem transpose
    {
        float w = __ldcg(&g_W2V[j]);
#pragma unroll
        for (int r = 0; r < 16; r++) s_mat[(i0 + r)*17 + c] = evr[r]*w;
        __syncthreads();
        float p0 = 0.f, p1 = 0.f, p2 = 0.f, p3 = 0.f;
#pragma unroll
        for (int k = 0; k < 16; k += 4) {
            p0 += s_mat[tid*17 + k+0];
            p1 += s_mat[tid*17 + k+1];
            p2 += s_mat[tid*17 + k+2];
            p3 += s_mat[tid*17 + k+3];
        }
        g_PART[blk*NE + tid] = (p0+p1)+(p2+p3);
    }
    gridbar(2);
    stageB(blk, tid, 0, out, s_stb);   // ent_0
    gridbar(3);

    // ========================= 64 sequential steps =========================
    float prevE = 0.f;   // previous ent for entity tid
    float pes   = 0.f;   // previous ent sum
    for (int t = 0; t < S; t++) {
        float c0   = __ldcg(&g_CHOICE[t*2+0]);
        float c1   = __ldcg(&g_CHOICE[t*2+1]);
        float scal = __ldcg(&g_SCAL[t]);

        // gather finalized ent (2KB) + per-block sums (issue early)
        float entv = __ldcg(&g_ENT[tid]);
        float sld = 0.f;
        if (wid < 2) sld = __ldcg(&g_SSUM8[tid]);

        // deferred snapshot of step t-1 (evr holds ev_t); overlaps gathers
        if (t > 0) {
            float* snap = out + OFF_ALL + (size_t)(t-1)*NE*H + j;
#pragma unroll
            for (int r = 0; r < 16; r++) __stcs(snap + (size_t)(i0 + r)*H, evr[r]);
        }

        float at = fmaf(c0, entv, c1*prevE);
        prevE = entv;
        s_attn[tid] = at;
        if (wid < 2) {
            float x = sld;
#pragma unroll
            for (int o = 16; o; o >>= 1) x += __shfl_xor_sync(0xffffffffu, x, o);
            if (lane == 0) s_r2[wid] = x;
        }
        __syncthreads();
        float esum = s_r2[0] + s_r2[1];
        float asum = fmaf(c0, esum, c1*pes);
        pes = esum;

        // bar_et partial (register ev)
        float bacc = 0.f;
#pragma unroll
        for (int r = 0; r < 16; r++) bacc += s_attn[i0 + r]*evr[r];
        s_part[s*17 + c] = bacc;
        __syncthreads();
        if (tid < RC) {
            float b0 = 0.f, b1 = 0.f;
#pragma unroll
            for (int q = 0; q < 32; q += 2) {
                b0 += s_part[(q+0)*17 + tid];
                b1 += s_part[(q+1)*17 + tid];
            }
            float bar = (b0 + b1) / asum;
            out[OFF_ENT + t*H + blk*RC + tid] = bar;
            s_kt[tid] = fmaxf(scal*bar, 0.f);
        }
        __syncthreads();
        float kt = s_kt[c];

        if (t < S-1) {
            float w2vn = __ldcg(&g_W2V[(t+1)*H + j]);
#pragma unroll
            for (int r = 0; r < 16; r++) {
                float a  = s_attn[i0 + r];
                float nv = fmaf(a, kt - evr[r], evr[r]);
                evr[r] = nv;
                s_mat[(i0 + r)*17 + c] = nv*w2vn;
            }
            __syncthreads();
            float p0 = 0.f, p1 = 0.f, p2 = 0.f, p3 = 0.f;
#pragma unroll
            for (int k = 0; k < 16; k += 4) {
                p0 += s_mat[tid*17 + k+0];
                p1 += s_mat[tid*17 + k+1];
                p2 += s_mat[tid*17 + k+2];
                p3 += s_mat[tid*17 + k+3];
            }
            g_PART[blk*NE + tid] = (p0+p1)+(p2+p3);
            gridbar((unsigned)(4 + 2*t));
            stageB(blk, tid, t+1, out, s_stb);
            gridbar((unsigned)(5 + 2*t));
        } else {
#pragma unroll
            for (int r = 0; r < 16; r++) {
                float a = s_attn[i0 + r];
                evr[r] = fmaf(a, kt - evr[r], evr[r]);
            }
            float* snap = out + OFF_ALL + (size_t)t*NE*H + j;
#pragma unroll
            for (int r = 0; r < 16; r++) __stcs(snap + (size_t)(i0 + r)*H, evr[r]);
        }
    }
}

// ---------------------------------------------------------------------------
extern "C" void kernel_launch(void* const* d_in, const int* in_sizes, int n_in,
                              void* d_out, int out_size)
{
    (void)in_sizes; (void)n_in; (void)out_size;
    const float* vv  = (const float*)d_in[0];
    const float* ev  = (const float*)d_in[1];
    const float* A1w = (const float*)d_in[2];
    const float* A1b = (const float*)d_in[3];
    const float* A2w = (const float*)d_in[4];
    const float* A2b = (const float*)d_in[5];
    const float* emb = (const float*)d_in[6];
    const float* W1w = (const float*)d_in[7];
    const float* W1b = (const float*)d_in[8];
    const float* W2w = (const float*)d_in[9];
    const float* W2b = (const float*)d_in[10];
    const float* W3w = (const float*)d_in[11];
    const float* W3b = (const float*)d_in[12];
    const float* W4w = (const float*)d_in[13];
    const float* W4b = (const float*)d_in[14];
    float* out = (float*)d_out;

    float *pHH, *pAC, *pGP3;
    cudaGetSymbolAddress((void**)&pHH,  g_HH);
    cudaGetSymbolAddress((void**)&pAC,  g_ACd);
    cudaGetSymbolAddress((void**)&pGP3, g_GP3);

    // 0: [h|hat] = relu(vv @ [A1w|W1w]^T + bias)  (also inits barrier)
    gemm32<<<dim3(64, 2), 256>>>(vv, H, A1w, W1w, 1024, A1b, W1b, pHH, 2048, H, 1);
    // 1: ac = sigmoid(h @ A2w^T + A2b)
    gemm32<<<dim3(16, 2), 256>>>(pHH, 2048, A2w, A2w, 1<<30, A2b, A2b, pAC, 512, H, 2);
    // 2: w2v partials
    gemm3<<<dim3(16, 8), 256>>>(W2w, pGP3, 1024, 1536, 192);
    // 3: fused finish + recurrence
    k_recurrent<<<RB, RT>>>(ev, emb, W2b, W3w, W3b, W4w, W4b, out);
}

// round 6
// speedup vs baseline: 1.0360x; 1.0360x over previous
#include <cuda_runtime.h>
#include <math.h>

// Problem dims
#define S  64
#define H  1024
#define V  512
#define WV 300
#define NE 512

// Recurrent kernel config
#define RB  64   // blocks; each owns RC columns of ev and 8 entities in stage B
#define RC  16
#define RT  512

// Output offsets (reference return order)
#define OFF_ENTP 0
#define OFF_ACP  (S*NE)
#define OFF_ENT  (OFF_ACP + S*V)
#define OFF_ALL  (OFF_ENT + S*H)
#define OFF_ACT  (OFF_ALL + (size_t)S*NE*H)

// Scratch (device globals; no allocation allowed)
__device__ __align__(16) float g_HH[64*2048];     // dense [relu(h) | relu(hat)]
__device__ __align__(16) float g_ACd[64*512];     // dense sigmoid(ac)
__device__ __align__(16) float g_GP3[8*64*1024];  // w2v split-K partials
__device__ __align__(16) float g_W2V[S*H];
__device__ float g_CHOICE[S*2];
__device__ float g_SCAL[S];
__device__ __align__(16) float g_PART[RB*NE];     // logit partials [part_block][entity]
__device__ __align__(16) float g_ENT[NE];         // finalized ent of current step
__device__ __align__(16) float g_SSUM8[RB];       // per-block 8-entity ent sums
__device__ __align__(128) unsigned g_flags[RB*32]; // per-block barrier slot, 128B apart

// ---------------------------------------------------------------------------
// Dense split-N GEMM: Out[64,N] = act( X[64,K] @ W[N,K]^T + b )
// Block (0,0) also resets the 64 barrier flag slots (runs before k_recurrent).
// ---------------------------------------------------------------------------
__global__ void __launch_bounds__(256) gemm32(
    const float* __restrict__ X, int xstride,
    const float* __restrict__ Wa, const float* __restrict__ Wb, int NB,
    const float* __restrict__ bA, const float* __restrict__ bB,
    float* __restrict__ Out, int ostride, int K, int act)
{
    if (blockIdx.x == 0 && blockIdx.y == 0 && threadIdx.x < RB) {
        g_flags[threadIdx.x*32] = 0u;
    }
    __shared__ __align__(8) float Xs[32][34];
    __shared__ __align__(8) float Ws[32][34];
    int tid = threadIdx.x;
    int tx = tid & 15, ty = tid >> 4;
    int n0 = blockIdx.x * 32;
    int m0 = blockIdx.y * 32;

    float a00 = 0.f, a01 = 0.f, a10 = 0.f, a11 = 0.f;

    for (int kc = 0; kc < K; kc += 32) {
#pragma unroll
        for (int i = 0; i < 4; i++) {
            int e = tid + 256*i; int row = e >> 5, kk = e & 31;
            Xs[kk][row] = X[(size_t)(m0 + row)*xstride + kc + kk];
        }
#pragma unroll
        for (int i = 0; i < 4; i++) {
            int e = tid + 256*i; int nr = e >> 5, kk = e & 31;
            int n = n0 + nr;
            const float* Wp = (n < NB) ? (Wa + (size_t)n*K) : (Wb + (size_t)(n - NB)*K);
            Ws[kk][nr] = Wp[kc + kk];
        }
        __syncthreads();
#pragma unroll
        for (int kk = 0; kk < 32; kk++) {
            float x0 = Xs[kk][ty*2], x1 = Xs[kk][ty*2+1];
            float w0 = Ws[kk][tx*2], w1 = Ws[kk][tx*2+1];
            a00 += x0*w0; a01 += x0*w1;
            a10 += x1*w0; a11 += x1*w1;
        }
        __syncthreads();
    }

    int n = n0 + tx*2;
    float b0 = (n   < NB) ? bA[n]   : bB[n   - NB];
    float b1 = (n+1 < NB) ? bA[n+1] : bB[n+1 - NB];
    float r[2][2] = {{a00 + b0, a01 + b1}, {a10 + b0, a11 + b1}};
#pragma unroll
    for (int q = 0; q < 2; q++)
#pragma unroll
        for (int p = 0; p < 2; p++) {
            float v = r[q][p];
            if (act == 1)      v = fmaxf(v, 0.f);
            else if (act == 2) v = 1.f/(1.f + expf(-v));
            Out[(size_t)(m0 + ty*2 + q)*ostride + n0 + tx*2 + p] = v;
        }
}

// ---------------------------------------------------------------------------
// Split-K GEMM for w2v partials: GP3[ky][64][1024] = [relu(hat)|sig(ac)] @ W2w^T
// ---------------------------------------------------------------------------
__global__ void __launch_bounds__(256) gemm3(
    const float* __restrict__ W, float* __restrict__ OutP, int N, int K, int kslice)
{
    __shared__ __align__(16) float XsT[32][68];
    __shared__ __align__(16) float WsT[32][68];
    int tid = threadIdx.x;
    int tx = tid & 15, ty = tid >> 4;
    int n0 = blockIdx.x * 64;
    int kc0 = blockIdx.y * kslice;

    float acc[4][4];
#pragma unroll
    for (int r = 0; r < 4; r++)
#pragma unroll
        for (int q = 0; q < 4; q++) acc[r][q] = 0.f;

    for (int kc = kc0; kc < kc0 + kslice; kc += 32) {
#pragma unroll
        for (int i = 0; i < 8; i++) {
            int e = tid + 256*i; int row = e >> 5, kk = e & 31;
            int k = kc + kk;
            XsT[kk][row] = (k < 1024) ? g_HH[row*2048 + 1024 + k]
                                      : g_ACd[row*512 + (k - 1024)];
        }
#pragma unroll
        for (int i = 0; i < 8; i++) {
            int e = tid + 256*i; int nr = e >> 5, kk = e & 31;
            WsT[kk][nr] = W[(size_t)(n0 + nr)*K + kc + kk];
        }
        __syncthreads();
#pragma unroll
        for (int kk = 0; kk < 32; kk++) {
            float4 xa = *(const float4*)&XsT[kk][ty*4];
            float4 wb = *(const float4*)&WsT[kk][tx*4];
            acc[0][0] += xa.x*wb.x; acc[0][1] += xa.x*wb.y; acc[0][2] += xa.x*wb.z; acc[0][3] += xa.x*wb.w;
            acc[1][0] += xa.y*wb.x; acc[1][1] += xa.y*wb.y; acc[1][2] += xa.y*wb.z; acc[1][3] += xa.y*wb.w;
            acc[2][0] += xa.z*wb.x; acc[2][1] += xa.z*wb.y; acc[2][2] += xa.z*wb.z; acc[2][3] += xa.z*wb.w;
            acc[3][0] += xa.w*wb.x; acc[3][1] += xa.w*wb.y; acc[3][2] += xa.w*wb.z; acc[3][3] += xa.w*wb.w;
        }
        __syncthreads();
    }
    float* Po = OutP + (size_t)blockIdx.y*64*N + n0;
#pragma unroll
    for (int r = 0; r < 4; r++) {
        float4 v = make_float4(acc[r][0], acc[r][1], acc[r][2], acc[r][3]);
        *(float4*)&Po[(size_t)(ty*4 + r)*N + tx*4] = v;
    }
}

// ---------------------------------------------------------------------------
// Contention-free flag barrier: each block release-stores its generation into
// its own 128B slot; warp 0 of every block polls all 64 slots (2 loads/lane).
// No central atomic, no central release round-trip. Generations are monotone.
// ---------------------------------------------------------------------------
__device__ __forceinline__ void gridbar(int tid, int blk, unsigned target)
{
    __syncthreads();   // orders all threads' prior writes before the release store
    if (tid < 32) {
        if (tid == 0)
            asm volatile("st.release.gpu.global.u32 [%0], %1;"
                         :: "l"(&g_flags[blk*32]), "r"(target) : "memory");
        unsigned a, b;
        do {
            asm volatile("ld.acquire.gpu.global.u32 %0, [%1];"
                         : "=r"(a) : "l"(&g_flags[tid*32]) : "memory");
            asm volatile("ld.acquire.gpu.global.u32 %0, [%1];"
                         : "=r"(b) : "l"(&g_flags[(tid+32)*32]) : "memory");
        } while (!__all_sync(0xffffffffu, (a >= target) && (b >= target)));
    }
    __syncthreads();
}

// ---------------------------------------------------------------------------
// Stage B: finalize ent for step tt. Block blk reduces entities [8blk, 8blk+8)
// across all 64 blocks' partials; writes g_ENT, ent_probs out row, g_SSUM8.
// ---------------------------------------------------------------------------
__device__ __forceinline__ void stageB(int blk, int tid, int tt,
                                       float* __restrict__ out,
                                       float* __restrict__ s_stb /*[16*8]*/)
{
    int p = tid >> 3, e = tid & 7;
    int lane = tid & 31, wid = tid >> 5;
    float v = __ldcg(&g_PART[p*NE + blk*8 + e]);
    v += __shfl_xor_sync(0xffffffffu, v, 8);
    v += __shfl_xor_sync(0xffffffffu, v, 16);
    if (lane < 8) s_stb[wid*8 + lane] = v;
    __syncthreads();
    if (tid < 8) {
        float lg = 0.f;
#pragma unroll
        for (int w = 0; w < 16; w++) lg += s_stb[w*8 + tid];
        float ent = 1.f/(1.f + expf(-lg));
        g_ENT[blk*8 + tid] = ent;
        out[OFF_ENTP + tt*NE + blk*8 + tid] = ent;
        float s8 = ent;
        s8 += __shfl_xor_sync(0xffu, s8, 4);
        s8 += __shfl_xor_sync(0xffu, s8, 2);
        s8 += __shfl_xor_sync(0xffu, s8, 1);
        if (tid == 0) g_SSUM8[blk] = s8;
    }
}

// ---------------------------------------------------------------------------
// Persistent recurrent kernel (launch index 3; profiled).
// ---------------------------------------------------------------------------
__global__ void __launch_bounds__(RT, 1) k_recurrent(
    const float* __restrict__ evin,
    const float* __restrict__ emb,
    const float* __restrict__ W2b,
    const float* __restrict__ W3w, const float* __restrict__ W3b,
    const float* __restrict__ W4w, const float* __restrict__ W4b,
    float* __restrict__ out)
{
    int tid = threadIdx.x;
    int blk = blockIdx.x;
    int c = tid & 15, s = tid >> 4;
    int j = blk*RC + c;
    int i0 = s*16;
    int lane = tid & 31, wid = tid >> 5;

    __shared__ float s_attn[NE];
    __shared__ float s_mat[NE*17];        // row-major padded transpose scratch
    __shared__ float s_part[32*17];
    __shared__ float s_kt[RC];
    __shared__ float s_red[16];
    __shared__ float s_r2[2];
    __shared__ float s_stb[16*8];
    __shared__ float s_sum;
    __shared__ float s_ac[V];
    __shared__ float s_bf[WV];
    __shared__ float s_cl[3];

    // issue ev load early (DRAM latency overlaps the smalls below)
    float evr[16];
#pragma unroll
    for (int r = 0; r < 16; r++) evr[r] = evin[(size_t)(i0 + r)*H + j];

    // ================= prologue: smalls for step t = blk =================
    {
        int t = blk;
        float a = g_ACd[t*V + tid];
        s_ac[tid] = a;
        out[OFF_ACP + t*V + tid] = a;
        float v = a;
#pragma unroll
        for (int o = 16; o; o >>= 1) v += __shfl_xor_sync(0xffffffffu, v, o);
        if (lane == 0) s_red[wid] = v;
        __syncthreads();
        if (tid < 16) {
            float x = s_red[tid];
#pragma unroll
            for (int o = 8; o; o >>= 1) x += __shfl_xor_sync(0x0000ffffu, x, o);
            if (tid == 0) s_sum = x;
        }
        __syncthreads();
        float acsum = s_sum;

        if (tid < WV) {
            float a0 = 0.f, a1 = 0.f, a2 = 0.f, a3 = 0.f;
            for (int i = 0; i < V; i += 4) {
                a0 += s_ac[i+0]*emb[(i+0)*WV + tid];
                a1 += s_ac[i+1]*emb[(i+1)*WV + tid];
                a2 += s_ac[i+2]*emb[(i+2)*WV + tid];
                a3 += s_ac[i+3]*emb[(i+3)*WV + tid];
            }
            float bf = ((a0+a1)+(a2+a3)) / acsum;
            s_bf[tid] = bf;
            out[OFF_ACT + t*WV + tid] = bf;
        }
        __syncthreads();

        float p = (tid < WV) ? s_bf[tid]*W4w[tid] : 0.f;
#pragma unroll
        for (int o = 16; o; o >>= 1) p += __shfl_xor_sync(0xffffffffu, p, o);
        if (lane == 0) s_red[wid] = p;
        __syncthreads();
        if (tid < 16) {
            float x = s_red[tid];
#pragma unroll
            for (int o = 8; o; o >>= 1) x += __shfl_xor_sync(0x0000ffffu, x, o);
            if (tid == 0) g_SCAL[t] = x + W4b[0];
        }

        if (wid < 3) {
            float a3v = 0.f;
            for (int k = lane; k < H; k += 32)
                a3v += g_HH[t*2048 + 1024 + k]*W3w[wid*H + k];
#pragma unroll
            for (int o = 16; o; o >>= 1) a3v += __shfl_xor_sync(0xffffffffu, a3v, o);
            if (lane == 0) s_cl[wid] = a3v + W3b[wid];
        }
        __syncthreads();
        if (tid == 0) {
            float m = fmaxf(s_cl[0], fmaxf(s_cl[1], s_cl[2]));
            float e0 = expf(s_cl[0]-m), e1 = expf(s_cl[1]-m), e2 = expf(s_cl[2]-m);
            float sm = e0 + e1 + e2;
            g_CHOICE[t*2+0] = e0/sm;
            g_CHOICE[t*2+1] = e1/sm;
        }

        // w2v[t] = W2b + sum_ky GP3[ky][t][:]
#pragma unroll
        for (int h2 = 0; h2 < 2; h2++) {
            int n = tid + 512*h2;
            float w = W2b[n];
#pragma unroll
            for (int ky = 0; ky < 8; ky++) w += g_GP3[ky*64*1024 + t*1024 + n];
            g_W2V[t*H + n] = w;
        }
    }
    gridbar(tid, blk, 1);

    // logit0 partials via smem transpose
    {
        float w = __ldcg(&g_W2V[j]);
#pragma unroll
        for (int r = 0; r < 16; r++) s_mat[(i0 + r)*17 + c] = evr[r]*w;
        __syncthreads();
        float p0 = 0.f, p1 = 0.f, p2 = 0.f, p3 = 0.f;
#pragma unroll
        for (int k = 0; k < 16; k += 4) {
            p0 += s_mat[tid*17 + k+0];
            p1 += s_mat[tid*17 + k+1];
            p2 += s_mat[tid*17 + k+2];
            p3 += s_mat[tid*17 + k+3];
        }
        g_PART[blk*NE + tid] = (p0+p1)+(p2+p3);
    }
    gridbar(tid, blk, 2);
    stageB(blk, tid, 0, out, s_stb);   // ent_0
    gridbar(tid, blk, 3);

    // ========================= 64 sequential steps =========================
    float prevE = 0.f;   // previous ent for entity tid
    float pes   = 0.f;   // previous ent sum
    for (int t = 0; t < S; t++) {
        float c0   = __ldcg(&g_CHOICE[t*2+0]);
        float c1   = __ldcg(&g_CHOICE[t*2+1]);
        float scal = __ldcg(&g_SCAL[t]);

        // gather finalized ent (2KB) + per-block sums (issue early)
        float entv = __ldcg(&g_ENT[tid]);
        float sld = 0.f;
        if (wid < 2) sld = __ldcg(&g_SSUM8[tid]);

        // deferred snapshot of step t-1 (evr holds ev_t); overlaps gathers
        if (t > 0) {
            float* snap = out + OFF_ALL + (size_t)(t-1)*NE*H + j;
#pragma unroll
            for (int r = 0; r < 16; r++) __stcs(snap + (size_t)(i0 + r)*H, evr[r]);
        }

        float at = fmaf(c0, entv, c1*prevE);
        prevE = entv;
        s_attn[tid] = at;
        if (wid < 2) {
            float x = sld;
#pragma unroll
            for (int o = 16; o; o >>= 1) x += __shfl_xor_sync(0xffffffffu, x, o);
            if (lane == 0) s_r2[wid] = x;
        }
        __syncthreads();
        float esum = s_r2[0] + s_r2[1];
        float asum = fmaf(c0, esum, c1*pes);
        pes = esum;

        // bar_et partial (register ev)
        float bacc = 0.f;
#pragma unroll
        for (int r = 0; r < 16; r++) bacc += s_attn[i0 + r]*evr[r];
        s_part[s*17 + c] = bacc;
        __syncthreads();
        if (tid < RC) {
            float b0 = 0.f, b1 = 0.f;
#pragma unroll
            for (int q = 0; q < 32; q += 2) {
                b0 += s_part[(q+0)*17 + tid];
                b1 += s_part[(q+1)*17 + tid];
            }
            float bar = (b0 + b1) / asum;
            out[OFF_ENT + t*H + blk*RC + tid] = bar;
            s_kt[tid] = fmaxf(scal*bar, 0.f);
        }
        __syncthreads();
        float kt = s_kt[c];

        if (t < S-1) {
            float w2vn = __ldcg(&g_W2V[(t+1)*H + j]);
#pragma unroll
            for (int r = 0; r < 16; r++) {
                float a  = s_attn[i0 + r];
                float nv = fmaf(a, kt - evr[r], evr[r]);
                evr[r] = nv;
                s_mat[(i0 + r)*17 + c] = nv*w2vn;
            }
            __syncthreads();
            float p0 = 0.f, p1 = 0.f, p2 = 0.f, p3 = 0.f;
#pragma unroll
            for (int k = 0; k < 16; k += 4) {
                p0 += s_mat[tid*17 + k+0];
                p1 += s_mat[tid*17 + k+1];
                p2 += s_mat[tid*17 + k+2];
                p3 += s_mat[tid*17 + k+3];
            }
            g_PART[blk*NE + tid] = (p0+p1)+(p2+p3);
            gridbar(tid, blk, (unsigned)(4 + 2*t));
            stageB(blk, tid, t+1, out, s_stb);
            gridbar(tid, blk, (unsigned)(5 + 2*t));
        } else {
#pragma unroll
            for (int r = 0; r < 16; r++) {
                float a = s_attn[i0 + r];
                evr[r] = fmaf(a, kt - evr[r], evr[r]);
            }
            float* snap = out + OFF_ALL + (size_t)t*NE*H + j;
#pragma unroll
            for (int r = 0; r < 16; r++) __stcs(snap + (size_t)(i0 + r)*H, evr[r]);
        }
    }
}

// ---------------------------------------------------------------------------
extern "C" void kernel_launch(void* const* d_in, const int* in_sizes, int n_in,
                              void* d_out, int out_size)
{
    (void)in_sizes; (void)n_in; (void)out_size;
    const float* vv  = (const float*)d_in[0];
    const float* ev  = (const float*)d_in[1];
    const float* A1w = (const float*)d_in[2];
    const float* A1b = (const float*)d_in[3];
    const float* A2w = (const float*)d_in[4];
    const float* A2b = (const float*)d_in[5];
    const float* emb = (const float*)d_in[6];
    const float* W1w = (const float*)d_in[7];
    const float* W1b = (const float*)d_in[8];
    const float* W2w = (const float*)d_in[9];
    const float* W2b = (const float*)d_in[10];
    const float* W3w = (const float*)d_in[11];
    const float* W3b = (const float*)d_in[12];
    const float* W4w = (const float*)d_in[13];
    const float* W4b = (const float*)d_in[14];
    float* out = (float*)d_out;

    float *pHH, *pAC, *pGP3;
    cudaGetSymbolAddress((void**)&pHH,  g_HH);
    cudaGetSymbolAddress((void**)&pAC,  g_ACd);
    cudaGetSymbolAddress((void**)&pGP3, g_GP3);

    // 0: [h|hat] = relu(vv @ [A1w|W1w]^T + bias)  (also resets barrier flags)
    gemm32<<<dim3(64, 2), 256>>>(vv, H, A1w, W1w, 1024, A1b, W1b, pHH, 2048, H, 1);
    // 1: ac = sigmoid(h @ A2w^T + A2b)
    gemm32<<<dim3(16, 2), 256>>>(pHH, 2048, A2w, A2w, 1<<30, A2b, A2b, pAC, 512, H, 2);
    // 2: w2v partials
    gemm3<<<dim3(16, 8), 256>>>(W2w, pGP3, 1024, 1536, 192);
    // 3: fused finish + recurrence
    k_recurrent<<<RB, RT>>>(ev, emb, W2b, W3w, W3b, W4w, W4b, out);
}